// round 15
// baseline (speedup 1.0000x reference)
#include <cuda_runtime.h>
#include <cuda_fp16.h>
#include <stdint.h>

#define FULLMASK 0xFFFFFFFFu

static const int MAX_N = 100000;
static const int DUMMY = MAX_N;       // all-zero dummy row (never written)
static const int PAD   = 128;
static const int PADSH = 7;

// padded strides for transposed weight tiles: ≡4 (mod 32) floats
static const int W1T_S = 132;
static const int W2T_S = 36;
static const int WM1T_S = 68;

// ---------------- device scratch (row MAX_N of h1/h2 = permanent zeros) ----------------
__device__ __half g_h1h[(MAX_N + 1) * 32];
__device__ __half g_z1[MAX_N * 32];
__device__ __half g_h2h[(MAX_N + 1) * 64];
__device__ __half g_z2[MAX_N * 64];
__device__ float  g_dinv[MAX_N];
__device__ int    g_cnt[MAX_N];       // zero at entry (module init / reset by k_mlp)
__device__ int    g_srcpad[MAX_N * PAD];

// ---------------- edge pass: padded CSR fill (+ zero out[]) ----------------
__global__ void k_fill(const int* __restrict__ src, const int* __restrict__ dst, int E,
                       float* __restrict__ out, int nbatch) {
    if (blockIdx.x == 0 && threadIdx.x < nbatch) out[threadIdx.x] = 0.0f;
    int e = blockIdx.x * blockDim.x + threadIdx.x;
    if (e < E) {
        int s = src[e];
        int d = dst[e];
        int slot = atomicAdd(&g_cnt[d], 1);
        if (slot < PAD) g_srcpad[(d << PADSH) + slot] = s;
    }
}

// ---------------- helpers ----------------
__device__ __forceinline__ void add_row(float* acc, uint4 v) {
    float2 f0 = __half22float2(*reinterpret_cast<__half2*>(&v.x));
    float2 f1 = __half22float2(*reinterpret_cast<__half2*>(&v.y));
    float2 f2 = __half22float2(*reinterpret_cast<__half2*>(&v.z));
    float2 f3 = __half22float2(*reinterpret_cast<__half2*>(&v.w));
    acc[0] += f0.x; acc[1] += f0.y;
    acc[2] += f1.x; acc[3] += f1.y;
    acc[4] += f2.x; acc[5] += f2.y;
    acc[6] += f3.x; acc[7] += f3.y;
}

__device__ __forceinline__ void unpack_row(float* out, uint4 v) {
    float2 f0 = __half22float2(*reinterpret_cast<__half2*>(&v.x));
    float2 f1 = __half22float2(*reinterpret_cast<__half2*>(&v.y));
    float2 f2 = __half22float2(*reinterpret_cast<__half2*>(&v.z));
    float2 f3 = __half22float2(*reinterpret_cast<__half2*>(&v.w));
    out[0] = f0.x; out[1] = f0.y;
    out[2] = f1.x; out[3] = f1.y;
    out[4] = f2.x; out[5] = f2.y;
    out[6] = f3.x; out[7] = f3.y;
}

__device__ __forceinline__ uint4 pack_row(const float* z) {
    uint4 r;
    __half2 h;
    h = __floats2half2_rn(z[0], z[1]); r.x = *reinterpret_cast<uint32_t*>(&h);
    h = __floats2half2_rn(z[2], z[3]); r.y = *reinterpret_cast<uint32_t*>(&h);
    h = __floats2half2_rn(z[4], z[5]); r.z = *reinterpret_cast<uint32_t*>(&h);
    h = __floats2half2_rn(z[6], z[7]); r.w = *reinterpret_cast<uint32_t*>(&h);
    return r;
}

__device__ __forceinline__ void pack_accs(const float* a, const float* b, __half2* h) {
#pragma unroll
    for (int i = 0; i < 4; i++)
        h[i] = __floats2half2_rn(a[2 * i] + b[2 * i], a[2 * i + 1] + b[2 * i + 1]);
}

__device__ __forceinline__ void hreduce_level(__half2* h, int mask) {
#pragma unroll
    for (int i = 0; i < 4; i++) {
        uint32_t u = *reinterpret_cast<uint32_t*>(&h[i]);
        uint32_t o = __shfl_xor_sync(FULLMASK, u, mask);
        h[i] = __hadd2(h[i], *reinterpret_cast<__half2*>(&o));
    }
}

__device__ __forceinline__ void hacc_to_float(const __half2* h, float* out) {
#pragma unroll
    for (int i = 0; i < 4; i++) {
        float2 f = __half22float2(h[i]);
        out[2 * i] = f.x; out[2 * i + 1] = f.y;
    }
}

// ---------------- GEMM1: h1' = (x @ W1) * dinv ----------------
__global__ void k_gemm1(const float* __restrict__ x, const float* __restrict__ W1, int n) {
    __shared__ float W1t[32 * W1T_S];      // W1t[o*W1T_S + k] = W1[k][o]
    __shared__ float xs[8][4][128];
    int tid = threadIdx.x;
    for (int idx = tid; idx < 128 * 32; idx += 256) {
        int k = idx >> 5, o = idx & 31;
        W1t[o * W1T_S + k] = W1[idx];
    }
    if (tid < 32) {
        int nd = blockIdx.x * 32 + tid;
        if (nd < n) g_dinv[nd] = rsqrtf(1.0f + (float)g_cnt[nd]);
    }
    __syncthreads();

    int lane = tid & 31;
    int w    = tid >> 5;
    int node0 = (blockIdx.x * 8 + w) * 4;

    float dv[4];
#pragma unroll
    for (int t = 0; t < 4; t++) {
        int nd = node0 + t;
        float4 v = make_float4(0.f, 0.f, 0.f, 0.f);
        if (nd < n) {
            v = reinterpret_cast<const float4*>(x + (size_t)nd * 128)[lane];
            dv[t] = rsqrtf(1.0f + (float)g_cnt[nd]);
        } else dv[t] = 0.f;
        *reinterpret_cast<float4*>(&xs[w][t][lane * 4]) = v;
    }
    __syncwarp();

    float a0 = 0.f, a1 = 0.f, a2 = 0.f, a3 = 0.f;
#pragma unroll
    for (int k4 = 0; k4 < 32; k4++) {
        float4 wv = *reinterpret_cast<float4*>(&W1t[lane * W1T_S + k4 * 4]);
        float4 x0 = *reinterpret_cast<float4*>(&xs[w][0][k4 * 4]);
        float4 x1 = *reinterpret_cast<float4*>(&xs[w][1][k4 * 4]);
        float4 x2 = *reinterpret_cast<float4*>(&xs[w][2][k4 * 4]);
        float4 x3 = *reinterpret_cast<float4*>(&xs[w][3][k4 * 4]);
        a0 = fmaf(x0.x, wv.x, fmaf(x0.y, wv.y, fmaf(x0.z, wv.z, fmaf(x0.w, wv.w, a0))));
        a1 = fmaf(x1.x, wv.x, fmaf(x1.y, wv.y, fmaf(x1.z, wv.z, fmaf(x1.w, wv.w, a1))));
        a2 = fmaf(x2.x, wv.x, fmaf(x2.y, wv.y, fmaf(x2.z, wv.z, fmaf(x2.w, wv.w, a2))));
        a3 = fmaf(x3.x, wv.x, fmaf(x3.y, wv.y, fmaf(x3.z, wv.z, fmaf(x3.w, wv.w, a3))));
    }
    float acc[4] = {a0, a1, a2, a3};
#pragma unroll
    for (int t = 0; t < 4; t++) {
        int nd = node0 + t;
        if (nd < n) g_h1h[(size_t)nd * 32 + lane] = __float2half(acc[t] * dv[t]);
    }
}

// ---------------- agg1 (pure): z1 = relu(di*(sum + self) + b1) ----------------
// warp per node; e = lane>>2, f = lane&3. Straight-line: 4 group loads in flight,
// invalid groups clamped to DUMMY (zero row) for unconditional accumulation.
__global__ void k_agg1(const float* __restrict__ b1, int n) {
    __shared__ float b1s[32];
    int tid = threadIdx.x;
    if (tid < 32) b1s[tid] = b1[tid];
    __syncthreads();

    int lane = tid & 31;
    int w    = tid >> 5;
    int node = blockIdx.x * 8 + w;
    if (node >= n) return;

    int e = lane >> 2;
    int f = lane & 3;

    float di   = g_dinv[node];
    int   base = node << PADSH;
    int   cnt  = g_cnt[node]; if (cnt > PAD) cnt = PAD;

    int i0 = g_srcpad[base + lane];

    float accA[8] = {0.f, 0.f, 0.f, 0.f, 0.f, 0.f, 0.f, 0.f};
    float accB[8] = {0.f, 0.f, 0.f, 0.f, 0.f, 0.f, 0.f, 0.f};

    // groups 0..3 cover edges 0..31
    int s0, s1, s2, s3;
    {
        int t0 = __shfl_sync(FULLMASK, i0, e);
        int t1 = __shfl_sync(FULLMASK, i0, 8 + e);
        int t2 = __shfl_sync(FULLMASK, i0, 16 + e);
        int t3 = __shfl_sync(FULLMASK, i0, 24 + e);
        s0 = (e < cnt)      ? t0 : DUMMY;
        s1 = (8 + e < cnt)  ? t1 : DUMMY;
        s2 = (16 + e < cnt) ? t2 : DUMMY;
        s3 = (24 + e < cnt) ? t3 : DUMMY;
    }
    uint4 v0 = __ldcg(reinterpret_cast<const uint4*>(&g_h1h[(size_t)s0 * 32 + f * 8]));
    uint4 v1 = __ldcg(reinterpret_cast<const uint4*>(&g_h1h[(size_t)s1 * 32 + f * 8]));
    uint4 v2 = __ldcg(reinterpret_cast<const uint4*>(&g_h1h[(size_t)s2 * 32 + f * 8]));
    uint4 v3 = __ldcg(reinterpret_cast<const uint4*>(&g_h1h[(size_t)s3 * 32 + f * 8]));
    add_row(accA, v0);
    add_row(accB, v1);
    add_row(accA, v2);
    add_row(accB, v3);

    if (cnt > 32) {                       // warp-uniform, ~7% of nodes
        int i1 = g_srcpad[base + 32 + lane];
        int t0 = __shfl_sync(FULLMASK, i1, e);
        int t1 = __shfl_sync(FULLMASK, i1, 8 + e);
        int t2 = __shfl_sync(FULLMASK, i1, 16 + e);
        int t3 = __shfl_sync(FULLMASK, i1, 24 + e);
        int u0 = (32 + e < cnt)      ? t0 : DUMMY;
        int u1 = (40 + e < cnt)      ? t1 : DUMMY;
        int u2 = (48 + e < cnt)      ? t2 : DUMMY;
        int u3 = (56 + e < cnt)      ? t3 : DUMMY;
        uint4 w0 = __ldcg(reinterpret_cast<const uint4*>(&g_h1h[(size_t)u0 * 32 + f * 8]));
        uint4 w1 = __ldcg(reinterpret_cast<const uint4*>(&g_h1h[(size_t)u1 * 32 + f * 8]));
        uint4 w2 = __ldcg(reinterpret_cast<const uint4*>(&g_h1h[(size_t)u2 * 32 + f * 8]));
        uint4 w3 = __ldcg(reinterpret_cast<const uint4*>(&g_h1h[(size_t)u3 * 32 + f * 8]));
        add_row(accA, w0);
        add_row(accB, w1);
        add_row(accA, w2);
        add_row(accB, w3);
        // degree > 64: extremely rare fallback
        for (int j = 64; j < cnt; j += 8) {
            int t = j + e;
            int s = (t < cnt) ? g_srcpad[base + t] : DUMMY;
            uint4 v = __ldcg(reinterpret_cast<const uint4*>(&g_h1h[(size_t)s * 32 + f * 8]));
            add_row(accA, v);
        }
    }

    __half2 hv[4];
    pack_accs(accA, accB, hv);
    hreduce_level(hv, 4);
    hreduce_level(hv, 8);
    hreduce_level(hv, 16);

    if (e == 0) {
        float acc[8];
        hacc_to_float(hv, acc);
        uint4 sv = *reinterpret_cast<const uint4*>(&g_h1h[(size_t)node * 32 + f * 8]);
        float sf[8];
        unpack_row(sf, sv);
        float z[8];
#pragma unroll
        for (int i = 0; i < 8; i++)
            z[i] = fmaxf(fmaf(di, acc[i] + sf[i], b1s[8 * f + i]), 0.0f);
        *reinterpret_cast<uint4*>(&g_z1[(size_t)node * 32 + f * 8]) = pack_row(z);
    }
}

// ---------------- GEMM2: h2' = (z1 @ W2) * dinv ----------------
__global__ void k_gemm2(const float* __restrict__ W2, int n) {
    __shared__ float W2t[64 * W2T_S];
    __shared__ float zs[8][4][32];
    int tid = threadIdx.x;
    for (int idx = tid; idx < 32 * 64; idx += 256) {
        int k = idx >> 6, o = idx & 63;
        W2t[o * W2T_S + k] = W2[idx];
    }
    __syncthreads();

    int lane = tid & 31;
    int w    = tid >> 5;
    int node0 = (blockIdx.x * 8 + w) * 4;

    if (lane < 16) {
        int t = lane >> 2, i = lane & 3;
        int nd = node0 + t;
        float zf[8] = {0.f, 0.f, 0.f, 0.f, 0.f, 0.f, 0.f, 0.f};
        if (nd < n) {
            uint4 v = *reinterpret_cast<const uint4*>(&g_z1[(size_t)nd * 32 + i * 8]);
            unpack_row(zf, v);
        }
        *reinterpret_cast<float4*>(&zs[w][t][i * 8])     = *reinterpret_cast<float4*>(&zf[0]);
        *reinterpret_cast<float4*>(&zs[w][t][i * 8 + 4]) = *reinterpret_cast<float4*>(&zf[4]);
    }
    __syncwarp();

    float m0[4] = {0.f, 0.f, 0.f, 0.f};
    float m1[4] = {0.f, 0.f, 0.f, 0.f};
#pragma unroll
    for (int k4 = 0; k4 < 8; k4++) {
        float4 w0 = *reinterpret_cast<float4*>(&W2t[lane * W2T_S + k4 * 4]);
        float4 w1 = *reinterpret_cast<float4*>(&W2t[(lane + 32) * W2T_S + k4 * 4]);
#pragma unroll
        for (int t = 0; t < 4; t++) {
            float4 zv = *reinterpret_cast<float4*>(&zs[w][t][k4 * 4]);
            m0[t] = fmaf(zv.x, w0.x, fmaf(zv.y, w0.y, fmaf(zv.z, w0.z, fmaf(zv.w, w0.w, m0[t]))));
            m1[t] = fmaf(zv.x, w1.x, fmaf(zv.y, w1.y, fmaf(zv.z, w1.z, fmaf(zv.w, w1.w, m1[t]))));
        }
    }
#pragma unroll
    for (int t = 0; t < 4; t++) {
        int nd = node0 + t;
        if (nd < n) {
            float dvt = g_dinv[nd];
            g_h2h[(size_t)nd * 64 + lane]      = __float2half(m0[t] * dvt);
            g_h2h[(size_t)nd * 64 + 32 + lane] = __float2half(m1[t] * dvt);
        }
    }
}

// ---------------- agg2 (pure): z2 = relu(di*(sum + self) + b2) ----------------
// warp per node; e = lane>>3, q = lane&7. Straight-line: 8 group loads (2 blocks of 4).
__global__ void k_agg2(const float* __restrict__ b2, int n) {
    __shared__ float b2s[64];
    int tid = threadIdx.x;
    if (tid < 64) b2s[tid] = b2[tid];
    __syncthreads();

    int lane = tid & 31;
    int w    = tid >> 5;
    int node = blockIdx.x * 8 + w;
    if (node >= n) return;

    int e = lane >> 3;
    int q = lane & 7;

    float di   = g_dinv[node];
    int   base = node << PADSH;
    int   cnt  = g_cnt[node]; if (cnt > PAD) cnt = PAD;

    int i0 = g_srcpad[base + lane];

    float accA[8] = {0.f, 0.f, 0.f, 0.f, 0.f, 0.f, 0.f, 0.f};
    float accB[8] = {0.f, 0.f, 0.f, 0.f, 0.f, 0.f, 0.f, 0.f};

    // groups 0..7 cover edges 0..31; two blocks of 4 independent loads
    int sg[8];
#pragma unroll
    for (int g = 0; g < 8; g++) {
        int t = __shfl_sync(FULLMASK, i0, g * 4 + e);
        sg[g] = (g * 4 + e < cnt) ? t : DUMMY;
    }
    {
        uint4 v0 = __ldcg(reinterpret_cast<const uint4*>(&g_h2h[(size_t)sg[0] * 64 + q * 8]));
        uint4 v1 = __ldcg(reinterpret_cast<const uint4*>(&g_h2h[(size_t)sg[1] * 64 + q * 8]));
        uint4 v2 = __ldcg(reinterpret_cast<const uint4*>(&g_h2h[(size_t)sg[2] * 64 + q * 8]));
        uint4 v3 = __ldcg(reinterpret_cast<const uint4*>(&g_h2h[(size_t)sg[3] * 64 + q * 8]));
        add_row(accA, v0);
        add_row(accB, v1);
        add_row(accA, v2);
        add_row(accB, v3);
    }
    {
        uint4 v0 = __ldcg(reinterpret_cast<const uint4*>(&g_h2h[(size_t)sg[4] * 64 + q * 8]));
        uint4 v1 = __ldcg(reinterpret_cast<const uint4*>(&g_h2h[(size_t)sg[5] * 64 + q * 8]));
        uint4 v2 = __ldcg(reinterpret_cast<const uint4*>(&g_h2h[(size_t)sg[6] * 64 + q * 8]));
        uint4 v3 = __ldcg(reinterpret_cast<const uint4*>(&g_h2h[(size_t)sg[7] * 64 + q * 8]));
        add_row(accA, v0);
        add_row(accB, v1);
        add_row(accA, v2);
        add_row(accB, v3);
    }

    if (cnt > 32) {                       // warp-uniform
        int i1 = g_srcpad[base + 32 + lane];
        int tg[8];
#pragma unroll
        for (int g = 0; g < 8; g++) {
            int t = __shfl_sync(FULLMASK, i1, g * 4 + e);
            tg[g] = (32 + g * 4 + e < cnt) ? t : DUMMY;
        }
#pragma unroll
        for (int g = 0; g < 8; g += 2) {
            uint4 va = __ldcg(reinterpret_cast<const uint4*>(&g_h2h[(size_t)tg[g] * 64 + q * 8]));
            uint4 vb = __ldcg(reinterpret_cast<const uint4*>(&g_h2h[(size_t)tg[g + 1] * 64 + q * 8]));
            add_row(accA, va);
            add_row(accB, vb);
        }
        for (int j = 64; j < cnt; j += 4) {   // degree > 64: rare
            int t = j + e;
            int s = (t < cnt) ? g_srcpad[base + t] : DUMMY;
            uint4 v = __ldcg(reinterpret_cast<const uint4*>(&g_h2h[(size_t)s * 64 + q * 8]));
            add_row(accA, v);
        }
    }

    __half2 hv[4];
    pack_accs(accA, accB, hv);
    hreduce_level(hv, 8);
    hreduce_level(hv, 16);

    if (e == 0) {
        float acc[8];
        hacc_to_float(hv, acc);
        uint4 sv = *reinterpret_cast<const uint4*>(&g_h2h[(size_t)node * 64 + q * 8]);
        float sf[8];
        unpack_row(sf, sv);
        float z[8];
#pragma unroll
        for (int i = 0; i < 8; i++)
            z[i] = fmaxf(fmaf(di, acc[i] + sf[i], b2s[8 * q + i]), 0.0f);
        *reinterpret_cast<uint4*>(&g_z2[(size_t)node * 64 + q * 8]) = pack_row(z);
    }
}

// ---------------- MLP head + scaled atomic output + g_cnt reset ----------------
__global__ void k_mlp(const float* __restrict__ Wm1, const float* __restrict__ bm1,
                      const float* __restrict__ Wm2, const float* __restrict__ bm2,
                      float* __restrict__ out,
                      int n, int num_nodes, int nbatch, float inv_num_nodes) {
    __shared__ float Wm1t[64 * WM1T_S];
    __shared__ float zs[8][4][64];
    __shared__ float bm1s[64];
    __shared__ float Wm2s[64];
    __shared__ float pv[32];
    __shared__ int   pb[32];

    int tid = threadIdx.x;
    for (int idx = tid; idx < 64 * 64; idx += 256) {
        int k = idx >> 6, o = idx & 63;
        Wm1t[o * WM1T_S + k] = Wm1[idx];
    }
    if (tid < 64) { bm1s[tid] = bm1[tid]; Wm2s[tid] = Wm2[tid]; }
    __syncthreads();

    int lane = tid & 31;
    int w    = tid >> 5;
    int node0 = (blockIdx.x * 8 + w) * 4;

    {
        int t = lane >> 3, i = lane & 7;
        int nd = node0 + t;
        float zf[8] = {0.f, 0.f, 0.f, 0.f, 0.f, 0.f, 0.f, 0.f};
        if (nd < n) {
            uint4 v = *reinterpret_cast<const uint4*>(&g_z2[(size_t)nd * 64 + i * 8]);
            unpack_row(zf, v);
        }
        *reinterpret_cast<float4*>(&zs[w][t][i * 8])     = *reinterpret_cast<float4*>(&zf[0]);
        *reinterpret_cast<float4*>(&zs[w][t][i * 8 + 4]) = *reinterpret_cast<float4*>(&zf[4]);
    }
    __syncwarp();

    float m0[4], m1[4];
#pragma unroll
    for (int t = 0; t < 4; t++) { m0[t] = bm1s[lane]; m1[t] = bm1s[lane + 32]; }

#pragma unroll
    for (int k4 = 0; k4 < 16; k4++) {
        float4 w0 = *reinterpret_cast<float4*>(&Wm1t[lane * WM1T_S + k4 * 4]);
        float4 w1 = *reinterpret_cast<float4*>(&Wm1t[(lane + 32) * WM1T_S + k4 * 4]);
#pragma unroll
        for (int t = 0; t < 4; t++) {
            float4 zv = *reinterpret_cast<float4*>(&zs[w][t][k4 * 4]);
            m0[t] = fmaf(zv.x, w0.x, fmaf(zv.y, w0.y, fmaf(zv.z, w0.z, fmaf(zv.w, w0.w, m0[t]))));
            m1[t] = fmaf(zv.x, w1.x, fmaf(zv.y, w1.y, fmaf(zv.z, w1.z, fmaf(zv.w, w1.w, m1[t]))));
        }
    }

    float wa = Wm2s[lane], wb = Wm2s[lane + 32];
#pragma unroll
    for (int t = 0; t < 4; t++) {
        float p = fmaxf(m0[t], 0.f) * wa + fmaxf(m1[t], 0.f) * wb;
        p += __shfl_xor_sync(FULLMASK, p, 16);
        p += __shfl_xor_sync(FULLMASK, p, 8);
        p += __shfl_xor_sync(FULLMASK, p, 4);
        p += __shfl_xor_sync(FULLMASK, p, 2);
        p += __shfl_xor_sync(FULLMASK, p, 1);
        if (lane == 0) {
            int nd = node0 + t;
            bool act = nd < n;
            pv[w * 4 + t] = act ? (p + bm2[0]) : 0.0f;
            int b = act ? (nd / num_nodes) : -1;
            if (b >= nbatch) b = -1;
            pb[w * 4 + t] = b;
        }
    }
    __syncthreads();

    if (tid == 0) {
        int bA = -1, bB = -1; float sA = 0.f, sB = 0.f;
        for (int k = 0; k < 32; k++) {
            int b = pb[k];
            if (b < 0) continue;
            if (bA < 0 || b == bA) { bA = b; sA += pv[k]; }
            else                   { bB = b; sB += pv[k]; }
        }
        if (bA >= 0) atomicAdd(&out[bA], sA * inv_num_nodes);
        if (bB >= 0) atomicAdd(&out[bB], sB * inv_num_nodes);
    }

    // reset g_cnt for the next graph replay (k_mlp never reads g_cnt; it is the last kernel)
    int gi = blockIdx.x * blockDim.x + tid;
    if (gi < n) g_cnt[gi] = 0;
}

// ---------------- host launch ----------------
extern "C" void kernel_launch(void* const* d_in, const int* in_sizes, int n_in,
                              void* d_out, int out_size) {
    const float* x   = (const float*)d_in[0];
    const float* W1c = (const float*)d_in[1];
    const float* b1c = (const float*)d_in[2];
    const float* W2c = (const float*)d_in[3];
    const float* b2c = (const float*)d_in[4];
    const float* Wm1 = (const float*)d_in[5];
    const float* bm1 = (const float*)d_in[6];
    const float* Wm2 = (const float*)d_in[7];
    const float* bm2 = (const float*)d_in[8];
    const int*   ei  = (const int*)d_in[9];
    float* out = (float*)d_out;

    int N = in_sizes[0] / 128;
    int E = in_sizes[9] / 2;
    const int* src = ei;
    const int* dst = ei + E;

    int nbatch = out_size;
    int num_nodes = N / (nbatch > 0 ? nbatch : 1);
    float inv_num_nodes = 1.0f / (float)num_nodes;

    k_fill<<<(E + 255) / 256, 256>>>(src, dst, E, out, nbatch);
    k_gemm1<<<(N + 31) / 32, 256>>>(x, W1c, N);
    k_agg1<<<(N + 7) / 8, 256>>>(b1c, N);
    k_gemm2<<<(N + 31) / 32, 256>>>(W2c, N);
    k_agg2<<<(N + 7) / 8, 256>>>(b2c, N);
    k_mlp<<<(N + 31) / 32, 256>>>(Wm1, bm1, Wm2, bm2, out, N, num_nodes, nbatch, inv_num_nodes);
}

// round 16
// speedup vs baseline: 1.1289x; 1.1289x over previous
#include <cuda_runtime.h>
#include <cuda_fp16.h>
#include <stdint.h>

#define FULLMASK 0xFFFFFFFFu

static const int MAX_N = 100000;
static const int PAD   = 128;
static const int PADSH = 7;

// padded strides for transposed weight tiles: ≡4 (mod 32) floats
static const int W1T_S = 132;
static const int W2T_S = 36;
static const int WM1T_S = 68;

// ---------------- device scratch ----------------
__device__ __half g_h1h[MAX_N * 32];   // (x @ W1) * dinv, fp16 (gather source L1)
__device__ __half g_z1[MAX_N * 32];    // relu(agg1) fp16
__device__ __half g_h2h[MAX_N * 64];   // (z1 @ W2) * dinv, fp16 (gather source L2)
__device__ __half g_z2[MAX_N * 64];    // relu(agg2) fp16
__device__ float  g_dinv[MAX_N];
__device__ int    g_cnt[MAX_N];
__device__ int    g_srcpad[MAX_N * PAD];

// ---------------- init: zero counters + output ----------------
__global__ void k_init(int n, float* __restrict__ out, int nbatch) {
    int i = blockIdx.x * blockDim.x + threadIdx.x;
    if (i < n) g_cnt[i] = 0;
    if (i < nbatch) out[i] = 0.0f;
}

// ---------------- edge pass: padded CSR fill ----------------
__global__ void k_fill(const int* __restrict__ src, const int* __restrict__ dst, int E) {
    int e = blockIdx.x * blockDim.x + threadIdx.x;
    if (e < E) {
        int s = src[e];
        int d = dst[e];
        int slot = atomicAdd(&g_cnt[d], 1);
        if (slot < PAD) g_srcpad[(d << PADSH) + slot] = s;
    }
}

// ---------------- helpers ----------------
__device__ __forceinline__ void add_row(float* acc, uint4 v) {
    float2 f0 = __half22float2(*reinterpret_cast<__half2*>(&v.x));
    float2 f1 = __half22float2(*reinterpret_cast<__half2*>(&v.y));
    float2 f2 = __half22float2(*reinterpret_cast<__half2*>(&v.z));
    float2 f3 = __half22float2(*reinterpret_cast<__half2*>(&v.w));
    acc[0] += f0.x; acc[1] += f0.y;
    acc[2] += f1.x; acc[3] += f1.y;
    acc[4] += f2.x; acc[5] += f2.y;
    acc[6] += f3.x; acc[7] += f3.y;
}

__device__ __forceinline__ void unpack_row(float* out, uint4 v) {
    float2 f0 = __half22float2(*reinterpret_cast<__half2*>(&v.x));
    float2 f1 = __half22float2(*reinterpret_cast<__half2*>(&v.y));
    float2 f2 = __half22float2(*reinterpret_cast<__half2*>(&v.z));
    float2 f3 = __half22float2(*reinterpret_cast<__half2*>(&v.w));
    out[0] = f0.x; out[1] = f0.y;
    out[2] = f1.x; out[3] = f1.y;
    out[4] = f2.x; out[5] = f2.y;
    out[6] = f3.x; out[7] = f3.y;
}

__device__ __forceinline__ uint4 pack_row(const float* z) {
    uint4 r;
    __half2 h;
    h = __floats2half2_rn(z[0], z[1]); r.x = *reinterpret_cast<uint32_t*>(&h);
    h = __floats2half2_rn(z[2], z[3]); r.y = *reinterpret_cast<uint32_t*>(&h);
    h = __floats2half2_rn(z[4], z[5]); r.z = *reinterpret_cast<uint32_t*>(&h);
    h = __floats2half2_rn(z[6], z[7]); r.w = *reinterpret_cast<uint32_t*>(&h);
    return r;
}

__device__ __forceinline__ void pack_accs(const float* a, const float* b, __half2* h) {
#pragma unroll
    for (int i = 0; i < 4; i++)
        h[i] = __floats2half2_rn(a[2 * i] + b[2 * i], a[2 * i + 1] + b[2 * i + 1]);
}

__device__ __forceinline__ void hreduce_level(__half2* h, int mask) {
#pragma unroll
    for (int i = 0; i < 4; i++) {
        uint32_t u = *reinterpret_cast<uint32_t*>(&h[i]);
        uint32_t o = __shfl_xor_sync(FULLMASK, u, mask);
        h[i] = __hadd2(h[i], *reinterpret_cast<__half2*>(&o));
    }
}

__device__ __forceinline__ void hacc_to_float(const __half2* h, float* out) {
#pragma unroll
    for (int i = 0; i < 4; i++) {
        float2 f = __half22float2(h[i]);
        out[2 * i] = f.x; out[2 * i + 1] = f.y;
    }
}

// ---------------- GEMM1: h1' = (x @ W1) * dinv ----------------
__global__ void k_gemm1(const float* __restrict__ x, const float* __restrict__ W1, int n) {
    __shared__ float W1t[32 * W1T_S];      // W1t[o*W1T_S + k] = W1[k][o]
    __shared__ float xs[8][4][128];
    int tid = threadIdx.x;
    for (int idx = tid; idx < 128 * 32; idx += 256) {
        int k = idx >> 5, o = idx & 31;
        W1t[o * W1T_S + k] = W1[idx];
    }
    if (tid < 32) {
        int nd = blockIdx.x * 32 + tid;
        if (nd < n) g_dinv[nd] = rsqrtf(1.0f + (float)g_cnt[nd]);
    }
    __syncthreads();

    int lane = tid & 31;
    int w    = tid >> 5;
    int node0 = (blockIdx.x * 8 + w) * 4;

    float dv[4];
#pragma unroll
    for (int t = 0; t < 4; t++) {
        int nd = node0 + t;
        float4 v = make_float4(0.f, 0.f, 0.f, 0.f);
        if (nd < n) {
            v = reinterpret_cast<const float4*>(x + (size_t)nd * 128)[lane];
            dv[t] = rsqrtf(1.0f + (float)g_cnt[nd]);
        } else dv[t] = 0.f;
        *reinterpret_cast<float4*>(&xs[w][t][lane * 4]) = v;
    }
    __syncwarp();

    float a0 = 0.f, a1 = 0.f, a2 = 0.f, a3 = 0.f;
#pragma unroll
    for (int k4 = 0; k4 < 32; k4++) {
        float4 wv = *reinterpret_cast<float4*>(&W1t[lane * W1T_S + k4 * 4]);
        float4 x0 = *reinterpret_cast<float4*>(&xs[w][0][k4 * 4]);
        float4 x1 = *reinterpret_cast<float4*>(&xs[w][1][k4 * 4]);
        float4 x2 = *reinterpret_cast<float4*>(&xs[w][2][k4 * 4]);
        float4 x3 = *reinterpret_cast<float4*>(&xs[w][3][k4 * 4]);
        a0 = fmaf(x0.x, wv.x, fmaf(x0.y, wv.y, fmaf(x0.z, wv.z, fmaf(x0.w, wv.w, a0))));
        a1 = fmaf(x1.x, wv.x, fmaf(x1.y, wv.y, fmaf(x1.z, wv.z, fmaf(x1.w, wv.w, a1))));
        a2 = fmaf(x2.x, wv.x, fmaf(x2.y, wv.y, fmaf(x2.z, wv.z, fmaf(x2.w, wv.w, a2))));
        a3 = fmaf(x3.x, wv.x, fmaf(x3.y, wv.y, fmaf(x3.z, wv.z, fmaf(x3.w, wv.w, a3))));
    }
    float acc[4] = {a0, a1, a2, a3};
#pragma unroll
    for (int t = 0; t < 4; t++) {
        int nd = node0 + t;
        if (nd < n) g_h1h[(size_t)nd * 32 + lane] = __float2half(acc[t] * dv[t]);
    }
}

// ---------------- agg1 (pure): z1 = relu(di*(sum + self) + b1) ---------------- (R14)
__global__ void k_agg1(const float* __restrict__ b1, int n) {
    __shared__ float b1s[32];
    int tid = threadIdx.x;
    if (tid < 32) b1s[tid] = b1[tid];
    __syncthreads();

    int lane = tid & 31;
    int w    = tid >> 5;
    int node = blockIdx.x * 8 + w;
    if (node >= n) return;

    int e = lane >> 2;
    int f = lane & 3;

    float di   = g_dinv[node];
    int   base = node << PADSH;
    int   cnt  = g_cnt[node]; if (cnt > PAD) cnt = PAD;

    int i0 = g_srcpad[base + lane];
    int i1 = (cnt > 32) ? g_srcpad[base + 32 + lane] : 0;
    int cregs = (cnt < 64) ? cnt : 64;

    float accA[8] = {0.f, 0.f, 0.f, 0.f, 0.f, 0.f, 0.f, 0.f};
    float accB[8] = {0.f, 0.f, 0.f, 0.f, 0.f, 0.f, 0.f, 0.f};

    int j = 0;
    for (; j + 16 <= cregs; j += 16) {
        int selA = (j < 32) ? i0 : i1;
        int selB = ((j + 8) < 32) ? i0 : i1;
        int sA = __shfl_sync(FULLMASK, selA, (j + e) & 31);
        int sB = __shfl_sync(FULLMASK, selB, (j + 8 + e) & 31);
        uint4 vA = __ldcg(reinterpret_cast<const uint4*>(&g_h1h[(size_t)sA * 32 + f * 8]));
        uint4 vB = __ldcg(reinterpret_cast<const uint4*>(&g_h1h[(size_t)sB * 32 + f * 8]));
        add_row(accA, vA);
        add_row(accB, vB);
    }
    if (j + 8 <= cregs) {
        int sel = (j < 32) ? i0 : i1;
        int s = __shfl_sync(FULLMASK, sel, (j + e) & 31);
        uint4 v = __ldcg(reinterpret_cast<const uint4*>(&g_h1h[(size_t)s * 32 + f * 8]));
        add_row(accA, v);
        j += 8;
    }
    for (; j + 8 <= cnt; j += 8) {
        int s = g_srcpad[base + j + e];
        uint4 v = __ldcg(reinterpret_cast<const uint4*>(&g_h1h[(size_t)s * 32 + f * 8]));
        add_row(accA, v);
    }
    if (j < cnt) {
        int t = j + e;
        bool valid = t < cnt;
        int s;
        if (t < 64) {
            int q0 = __shfl_sync(FULLMASK, i0, t & 31);
            int q1 = __shfl_sync(FULLMASK, i1, t & 31);
            s = (t < 32) ? q0 : q1;
        } else s = valid ? g_srcpad[base + t] : node;
        uint4 v = __ldcg(reinterpret_cast<const uint4*>(&g_h1h[(size_t)s * 32 + f * 8]));
        if (valid) add_row(accB, v);
    }

    __half2 hv[4];
    pack_accs(accA, accB, hv);
    hreduce_level(hv, 4);
    hreduce_level(hv, 8);
    hreduce_level(hv, 16);

    if (e == 0) {
        float acc[8];
        hacc_to_float(hv, acc);
        uint4 sv = *reinterpret_cast<const uint4*>(&g_h1h[(size_t)node * 32 + f * 8]);
        float sf[8];
        unpack_row(sf, sv);
        float z[8];
#pragma unroll
        for (int i = 0; i < 8; i++)
            z[i] = fmaxf(fmaf(di, acc[i] + sf[i], b1s[8 * f + i]), 0.0f);
        *reinterpret_cast<uint4*>(&g_z1[(size_t)node * 32 + f * 8]) = pack_row(z);
    }
}

// ---------------- GEMM2: h2' = (z1 @ W2) * dinv  (8 nodes/warp) ----------------
__global__ void k_gemm2(const float* __restrict__ W2, int n) {
    __shared__ float W2t[64 * W2T_S];       // W2t[o*W2T_S + k] = W2[k][o]
    __shared__ float zs[8][8][32];
    int tid = threadIdx.x;
    for (int idx = tid; idx < 32 * 64; idx += 256) {
        int k = idx >> 6, o = idx & 63;
        W2t[o * W2T_S + k] = W2[idx];
    }
    __syncthreads();

    int lane = tid & 31;
    int w    = tid >> 5;
    int node0 = (blockIdx.x * 8 + w) * 8;

    {
        int t = lane >> 2, i = lane & 3;      // 8 nodes x 4 blocks = 32 lanes
        int nd = node0 + t;
        float zf[8] = {0.f, 0.f, 0.f, 0.f, 0.f, 0.f, 0.f, 0.f};
        if (nd < n) {
            uint4 v = *reinterpret_cast<const uint4*>(&g_z1[(size_t)nd * 32 + i * 8]);
            unpack_row(zf, v);
        }
        *reinterpret_cast<float4*>(&zs[w][t][i * 8])     = *reinterpret_cast<float4*>(&zf[0]);
        *reinterpret_cast<float4*>(&zs[w][t][i * 8 + 4]) = *reinterpret_cast<float4*>(&zf[4]);
    }
    __syncwarp();

    float m0[8] = {0.f, 0.f, 0.f, 0.f, 0.f, 0.f, 0.f, 0.f};
    float m1[8] = {0.f, 0.f, 0.f, 0.f, 0.f, 0.f, 0.f, 0.f};
#pragma unroll
    for (int k4 = 0; k4 < 8; k4++) {
        float4 w0 = *reinterpret_cast<float4*>(&W2t[lane * W2T_S + k4 * 4]);
        float4 w1 = *reinterpret_cast<float4*>(&W2t[(lane + 32) * W2T_S + k4 * 4]);
#pragma unroll
        for (int t = 0; t < 8; t++) {
            float4 zv = *reinterpret_cast<float4*>(&zs[w][t][k4 * 4]);
            m0[t] = fmaf(zv.x, w0.x, fmaf(zv.y, w0.y, fmaf(zv.z, w0.z, fmaf(zv.w, w0.w, m0[t]))));
            m1[t] = fmaf(zv.x, w1.x, fmaf(zv.y, w1.y, fmaf(zv.z, w1.z, fmaf(zv.w, w1.w, m1[t]))));
        }
    }
#pragma unroll
    for (int t = 0; t < 8; t++) {
        int nd = node0 + t;
        if (nd < n) {
            float dvt = g_dinv[nd];
            g_h2h[(size_t)nd * 64 + lane]      = __float2half(m0[t] * dvt);
            g_h2h[(size_t)nd * 64 + 32 + lane] = __float2half(m1[t] * dvt);
        }
    }
}

// ---------------- agg2 (pure): z2 = relu(di*(sum + self) + b2) ---------------- (R14)
__global__ void k_agg2(const float* __restrict__ b2, int n) {
    __shared__ float b2s[64];
    int tid = threadIdx.x;
    if (tid < 64) b2s[tid] = b2[tid];
    __syncthreads();

    int lane = tid & 31;
    int w    = tid >> 5;
    int node = blockIdx.x * 8 + w;
    if (node >= n) return;

    int e = lane >> 3;
    int q = lane & 7;

    float di   = g_dinv[node];
    int   base = node << PADSH;
    int   cnt  = g_cnt[node]; if (cnt > PAD) cnt = PAD;

    int i0 = g_srcpad[base + lane];
    int i1 = (cnt > 32) ? g_srcpad[base + 32 + lane] : 0;
    int cregs = (cnt < 64) ? cnt : 64;

    float accA[8] = {0.f, 0.f, 0.f, 0.f, 0.f, 0.f, 0.f, 0.f};
    float accB[8] = {0.f, 0.f, 0.f, 0.f, 0.f, 0.f, 0.f, 0.f};

    int j = 0;
    for (; j + 8 <= cregs; j += 8) {
        int selA = (j < 32) ? i0 : i1;
        int selB = ((j + 4) < 32) ? i0 : i1;
        int sA = __shfl_sync(FULLMASK, selA, (j + e) & 31);
        int sB = __shfl_sync(FULLMASK, selB, (j + 4 + e) & 31);
        uint4 vA = __ldcg(reinterpret_cast<const uint4*>(&g_h2h[(size_t)sA * 64 + q * 8]));
        uint4 vB = __ldcg(reinterpret_cast<const uint4*>(&g_h2h[(size_t)sB * 64 + q * 8]));
        add_row(accA, vA);
        add_row(accB, vB);
    }
    if (j + 4 <= cregs) {
        int sel = (j < 32) ? i0 : i1;
        int s = __shfl_sync(FULLMASK, sel, (j + e) & 31);
        uint4 v = __ldcg(reinterpret_cast<const uint4*>(&g_h2h[(size_t)s * 64 + q * 8]));
        add_row(accA, v);
        j += 4;
    }
    for (; j + 4 <= cnt; j += 4) {
        int s = g_srcpad[base + j + e];
        uint4 v = __ldcg(reinterpret_cast<const uint4*>(&g_h2h[(size_t)s * 64 + q * 8]));
        add_row(accA, v);
    }
    if (j < cnt) {
        int t = j + e;
        bool valid = t < cnt;
        int s;
        if (t < 64) {
            int q0 = __shfl_sync(FULLMASK, i0, t & 31);
            int q1 = __shfl_sync(FULLMASK, i1, t & 31);
            s = (t < 32) ? q0 : q1;
        } else s = valid ? g_srcpad[base + t] : node;
        uint4 v = __ldcg(reinterpret_cast<const uint4*>(&g_h2h[(size_t)s * 64 + q * 8]));
        if (valid) add_row(accB, v);
    }

    __half2 hv[4];
    pack_accs(accA, accB, hv);
    hreduce_level(hv, 8);
    hreduce_level(hv, 16);

    if (e == 0) {
        float acc[8];
        hacc_to_float(hv, acc);
        uint4 sv = *reinterpret_cast<const uint4*>(&g_h2h[(size_t)node * 64 + q * 8]);
        float sf[8];
        unpack_row(sf, sv);
        float z[8];
#pragma unroll
        for (int i = 0; i < 8; i++)
            z[i] = fmaxf(fmaf(di, acc[i] + sf[i], b2s[8 * q + i]), 0.0f);
        *reinterpret_cast<uint4*>(&g_z2[(size_t)node * 64 + q * 8]) = pack_row(z);
    }
}

// ---------------- MLP head + scaled atomic output  (8 nodes/warp) ----------------
__global__ void k_mlp(const float* __restrict__ Wm1, const float* __restrict__ bm1,
                      const float* __restrict__ Wm2, const float* __restrict__ bm2,
                      float* __restrict__ out,
                      int n, int num_nodes, int nbatch, float inv_num_nodes) {
    __shared__ float Wm1t[64 * WM1T_S];
    __shared__ float zs[8][8][64];
    __shared__ float bm1s[64];
    __shared__ float Wm2s[64];
    __shared__ float pv[64];
    __shared__ int   pb[64];

    int tid = threadIdx.x;
    for (int idx = tid; idx < 64 * 64; idx += 256) {
        int k = idx >> 6, o = idx & 63;
        Wm1t[o * WM1T_S + k] = Wm1[idx];
    }
    if (tid < 64) { bm1s[tid] = bm1[tid]; Wm2s[tid] = Wm2[tid]; }
    __syncthreads();

    int lane = tid & 31;
    int w    = tid >> 5;
    int node0 = (blockIdx.x * 8 + w) * 8;

    // stage 8 node rows (8 uint4 each = 64 uint4) -> 2 per lane
#pragma unroll
    for (int r = 0; r < 2; r++) {
        int idx = r * 32 + lane;
        int t = idx >> 3, i = idx & 7;
        int nd = node0 + t;
        float zf[8] = {0.f, 0.f, 0.f, 0.f, 0.f, 0.f, 0.f, 0.f};
        if (nd < n) {
            uint4 v = *reinterpret_cast<const uint4*>(&g_z2[(size_t)nd * 64 + i * 8]);
            unpack_row(zf, v);
        }
        *reinterpret_cast<float4*>(&zs[w][t][i * 8])     = *reinterpret_cast<float4*>(&zf[0]);
        *reinterpret_cast<float4*>(&zs[w][t][i * 8 + 4]) = *reinterpret_cast<float4*>(&zf[4]);
    }
    __syncwarp();

    float m0[8], m1[8];
#pragma unroll
    for (int t = 0; t < 8; t++) { m0[t] = bm1s[lane]; m1[t] = bm1s[lane + 32]; }

#pragma unroll
    for (int k4 = 0; k4 < 16; k4++) {
        float4 w0 = *reinterpret_cast<float4*>(&Wm1t[lane * WM1T_S + k4 * 4]);
        float4 w1 = *reinterpret_cast<float4*>(&Wm1t[(lane + 32) * WM1T_S + k4 * 4]);
#pragma unroll
        for (int t = 0; t < 8; t++) {
            float4 zv = *reinterpret_cast<float4*>(&zs[w][t][k4 * 4]);
            m0[t] = fmaf(zv.x, w0.x, fmaf(zv.y, w0.y, fmaf(zv.z, w0.z, fmaf(zv.w, w0.w, m0[t]))));
            m1[t] = fmaf(zv.x, w1.x, fmaf(zv.y, w1.y, fmaf(zv.z, w1.z, fmaf(zv.w, w1.w, m1[t]))));
        }
    }

    float wa = Wm2s[lane], wb = Wm2s[lane + 32];
#pragma unroll
    for (int t = 0; t < 8; t++) {
        float p = fmaxf(m0[t], 0.f) * wa + fmaxf(m1[t], 0.f) * wb;
        p += __shfl_xor_sync(FULLMASK, p, 16);
        p += __shfl_xor_sync(FULLMASK, p, 8);
        p += __shfl_xor_sync(FULLMASK, p, 4);
        p += __shfl_xor_sync(FULLMASK, p, 2);
        p += __shfl_xor_sync(FULLMASK, p, 1);
        if (lane == 0) {
            int nd = node0 + t;
            bool act = nd < n;
            pv[w * 8 + t] = act ? (p + bm2[0]) : 0.0f;
            int b = act ? (nd / num_nodes) : -1;
            if (b >= nbatch) b = -1;
            pb[w * 8 + t] = b;
        }
    }
    __syncthreads();

    if (tid == 0) {
        int bA = -1, bB = -1; float sA = 0.f, sB = 0.f;
        for (int k = 0; k < 64; k++) {
            int b = pb[k];
            if (b < 0) continue;
            if (bA < 0 || b == bA) { bA = b; sA += pv[k]; }
            else                   { bB = b; sB += pv[k]; }
        }
        if (bA >= 0) atomicAdd(&out[bA], sA * inv_num_nodes);
        if (bB >= 0) atomicAdd(&out[bB], sB * inv_num_nodes);
    }
}

// ---------------- host launch ----------------
extern "C" void kernel_launch(void* const* d_in, const int* in_sizes, int n_in,
                              void* d_out, int out_size) {
    const float* x   = (const float*)d_in[0];
    const float* W1c = (const float*)d_in[1];
    const float* b1c = (const float*)d_in[2];
    const float* W2c = (const float*)d_in[3];
    const float* b2c = (const float*)d_in[4];
    const float* Wm1 = (const float*)d_in[5];
    const float* bm1 = (const float*)d_in[6];
    const float* Wm2 = (const float*)d_in[7];
    const float* bm2 = (const float*)d_in[8];
    const int*   ei  = (const int*)d_in[9];
    float* out = (float*)d_out;

    int N = in_sizes[0] / 128;
    int E = in_sizes[9] / 2;
    const int* src = ei;
    const int* dst = ei + E;

    int nbatch = out_size;
    int num_nodes = N / (nbatch > 0 ? nbatch : 1);
    float inv_num_nodes = 1.0f / (float)num_nodes;

    k_init<<<(N + 255) / 256, 256>>>(N, out, nbatch);
    k_fill<<<(E + 255) / 256, 256>>>(src, dst, E);
    k_gemm1<<<(N + 31) / 32, 256>>>(x, W1c, N);
    k_agg1<<<(N + 7) / 8, 256>>>(b1c, N);
    k_gemm2<<<(N + 63) / 64, 256>>>(W2c, N);
    k_agg2<<<(N + 7) / 8, 256>>>(b2c, N);
    k_mlp<<<(N + 63) / 64, 256>>>(Wm1, bm1, Wm2, bm2, out, N, num_nodes, nbatch, inv_num_nodes);
}

// round 17
// speedup vs baseline: 1.1541x; 1.0224x over previous
#include <cuda_runtime.h>
#include <cuda_fp16.h>
#include <stdint.h>

#define FULLMASK 0xFFFFFFFFu

static const int MAX_N = 100000;
static const int PAD   = 128;
static const int PADSH = 7;

// padded strides for transposed weight tiles: ≡4 (mod 32) floats
static const int W1T_S = 132;
static const int W2T_S = 36;
static const int WM1T_S = 68;

// ---------------- device scratch ----------------
__device__ __half g_h1h[MAX_N * 32];   // (x @ W1) * dinv, fp16
__device__ __half g_z1[MAX_N * 32];    // relu(agg1) fp16
__device__ __half g_h2h[MAX_N * 64];   // (z1 @ W2) * dinv, fp16
__device__ __half g_z2[MAX_N * 64];    // relu(agg2) fp16
__device__ float  g_dinv[MAX_N];
__device__ int    g_cnt[MAX_N];        // zero at entry (module init / reset by k_mlp tail)
__device__ int    g_srcpad[MAX_N * PAD];

// ---------------- edge pass: padded CSR fill (+ zero out[]) ----------------
__global__ void k_fill(const int* __restrict__ src, const int* __restrict__ dst, int E,
                       float* __restrict__ out, int nbatch) {
    if (blockIdx.x == 0 && threadIdx.x < nbatch) out[threadIdx.x] = 0.0f;
    int e = blockIdx.x * blockDim.x + threadIdx.x;
    if (e < E) {
        int s = src[e];
        int d = dst[e];
        int slot = atomicAdd(&g_cnt[d], 1);
        if (slot < PAD) g_srcpad[(d << PADSH) + slot] = s;
    }
}

// ---------------- helpers ----------------
__device__ __forceinline__ void add_row(float* acc, uint4 v) {
    float2 f0 = __half22float2(*reinterpret_cast<__half2*>(&v.x));
    float2 f1 = __half22float2(*reinterpret_cast<__half2*>(&v.y));
    float2 f2 = __half22float2(*reinterpret_cast<__half2*>(&v.z));
    float2 f3 = __half22float2(*reinterpret_cast<__half2*>(&v.w));
    acc[0] += f0.x; acc[1] += f0.y;
    acc[2] += f1.x; acc[3] += f1.y;
    acc[4] += f2.x; acc[5] += f2.y;
    acc[6] += f3.x; acc[7] += f3.y;
}

__device__ __forceinline__ void unpack_row(float* out, uint4 v) {
    float2 f0 = __half22float2(*reinterpret_cast<__half2*>(&v.x));
    float2 f1 = __half22float2(*reinterpret_cast<__half2*>(&v.y));
    float2 f2 = __half22float2(*reinterpret_cast<__half2*>(&v.z));
    float2 f3 = __half22float2(*reinterpret_cast<__half2*>(&v.w));
    out[0] = f0.x; out[1] = f0.y;
    out[2] = f1.x; out[3] = f1.y;
    out[4] = f2.x; out[5] = f2.y;
    out[6] = f3.x; out[7] = f3.y;
}

__device__ __forceinline__ uint4 pack_row(const float* z) {
    uint4 r;
    __half2 h;
    h = __floats2half2_rn(z[0], z[1]); r.x = *reinterpret_cast<uint32_t*>(&h);
    h = __floats2half2_rn(z[2], z[3]); r.y = *reinterpret_cast<uint32_t*>(&h);
    h = __floats2half2_rn(z[4], z[5]); r.z = *reinterpret_cast<uint32_t*>(&h);
    h = __floats2half2_rn(z[6], z[7]); r.w = *reinterpret_cast<uint32_t*>(&h);
    return r;
}

__device__ __forceinline__ void pack_accs(const float* a, const float* b, __half2* h) {
#pragma unroll
    for (int i = 0; i < 4; i++)
        h[i] = __floats2half2_rn(a[2 * i] + b[2 * i], a[2 * i + 1] + b[2 * i + 1]);
}

__device__ __forceinline__ void hreduce_level(__half2* h, int mask) {
#pragma unroll
    for (int i = 0; i < 4; i++) {
        uint32_t u = *reinterpret_cast<uint32_t*>(&h[i]);
        uint32_t o = __shfl_xor_sync(FULLMASK, u, mask);
        h[i] = __hadd2(h[i], *reinterpret_cast<__half2*>(&o));
    }
}

__device__ __forceinline__ void hacc_to_float(const __half2* h, float* out) {
#pragma unroll
    for (int i = 0; i < 4; i++) {
        float2 f = __half22float2(h[i]);
        out[2 * i] = f.x; out[2 * i + 1] = f.y;
    }
}

// ---------------- GEMM1: h1' = (x @ W1) * dinv ----------------
__global__ void k_gemm1(const float* __restrict__ x, const float* __restrict__ W1, int n) {
    __shared__ float W1t[32 * W1T_S];      // W1t[o*W1T_S + k] = W1[k][o]
    __shared__ float xs[8][4][128];
    int tid = threadIdx.x;
    for (int idx = tid; idx < 128 * 32; idx += 256) {
        int k = idx >> 5, o = idx & 31;
        W1t[o * W1T_S + k] = W1[idx];
    }
    if (tid < 32) {
        int nd = blockIdx.x * 32 + tid;
        if (nd < n) g_dinv[nd] = rsqrtf(1.0f + (float)g_cnt[nd]);
    }
    __syncthreads();

    int lane = tid & 31;
    int w    = tid >> 5;
    int node0 = (blockIdx.x * 8 + w) * 4;

    float dv[4];
#pragma unroll
    for (int t = 0; t < 4; t++) {
        int nd = node0 + t;
        float4 v = make_float4(0.f, 0.f, 0.f, 0.f);
        if (nd < n) {
            v = __ldcg(reinterpret_cast<const float4*>(x + (size_t)nd * 128) + lane);
            dv[t] = rsqrtf(1.0f + (float)g_cnt[nd]);
        } else dv[t] = 0.f;
        *reinterpret_cast<float4*>(&xs[w][t][lane * 4]) = v;
    }
    __syncwarp();

    float a0 = 0.f, a1 = 0.f, a2 = 0.f, a3 = 0.f;
#pragma unroll
    for (int k4 = 0; k4 < 32; k4++) {
        float4 wv = *reinterpret_cast<float4*>(&W1t[lane * W1T_S + k4 * 4]);
        float4 x0 = *reinterpret_cast<float4*>(&xs[w][0][k4 * 4]);
        float4 x1 = *reinterpret_cast<float4*>(&xs[w][1][k4 * 4]);
        float4 x2 = *reinterpret_cast<float4*>(&xs[w][2][k4 * 4]);
        float4 x3 = *reinterpret_cast<float4*>(&xs[w][3][k4 * 4]);
        a0 = fmaf(x0.x, wv.x, fmaf(x0.y, wv.y, fmaf(x0.z, wv.z, fmaf(x0.w, wv.w, a0))));
        a1 = fmaf(x1.x, wv.x, fmaf(x1.y, wv.y, fmaf(x1.z, wv.z, fmaf(x1.w, wv.w, a1))));
        a2 = fmaf(x2.x, wv.x, fmaf(x2.y, wv.y, fmaf(x2.z, wv.z, fmaf(x2.w, wv.w, a2))));
        a3 = fmaf(x3.x, wv.x, fmaf(x3.y, wv.y, fmaf(x3.z, wv.z, fmaf(x3.w, wv.w, a3))));
    }
    float acc[4] = {a0, a1, a2, a3};
#pragma unroll
    for (int t = 0; t < 4; t++) {
        int nd = node0 + t;
        if (nd < n) g_h1h[(size_t)nd * 32 + lane] = __float2half(acc[t] * dv[t]);
    }
}

// ---------------- agg1 (pure): z1 = relu(di*(sum + self) + b1) ---------------- (R14)
__global__ void k_agg1(const float* __restrict__ b1, int n) {
    __shared__ float b1s[32];
    int tid = threadIdx.x;
    if (tid < 32) b1s[tid] = b1[tid];
    __syncthreads();

    int lane = tid & 31;
    int w    = tid >> 5;
    int node = blockIdx.x * 8 + w;
    if (node >= n) return;

    int e = lane >> 2;
    int f = lane & 3;

    float di   = g_dinv[node];
    int   base = node << PADSH;
    int   cnt  = g_cnt[node]; if (cnt > PAD) cnt = PAD;

    int i0 = g_srcpad[base + lane];
    int i1 = (cnt > 32) ? g_srcpad[base + 32 + lane] : 0;
    int cregs = (cnt < 64) ? cnt : 64;

    float accA[8] = {0.f, 0.f, 0.f, 0.f, 0.f, 0.f, 0.f, 0.f};
    float accB[8] = {0.f, 0.f, 0.f, 0.f, 0.f, 0.f, 0.f, 0.f};

    int j = 0;
    for (; j + 16 <= cregs; j += 16) {
        int selA = (j < 32) ? i0 : i1;
        int selB = ((j + 8) < 32) ? i0 : i1;
        int sA = __shfl_sync(FULLMASK, selA, (j + e) & 31);
        int sB = __shfl_sync(FULLMASK, selB, (j + 8 + e) & 31);
        uint4 vA = __ldcg(reinterpret_cast<const uint4*>(&g_h1h[(size_t)sA * 32 + f * 8]));
        uint4 vB = __ldcg(reinterpret_cast<const uint4*>(&g_h1h[(size_t)sB * 32 + f * 8]));
        add_row(accA, vA);
        add_row(accB, vB);
    }
    if (j + 8 <= cregs) {
        int sel = (j < 32) ? i0 : i1;
        int s = __shfl_sync(FULLMASK, sel, (j + e) & 31);
        uint4 v = __ldcg(reinterpret_cast<const uint4*>(&g_h1h[(size_t)s * 32 + f * 8]));
        add_row(accA, v);
        j += 8;
    }
    for (; j + 8 <= cnt; j += 8) {
        int s = g_srcpad[base + j + e];
        uint4 v = __ldcg(reinterpret_cast<const uint4*>(&g_h1h[(size_t)s * 32 + f * 8]));
        add_row(accA, v);
    }
    if (j < cnt) {
        int t = j + e;
        bool valid = t < cnt;
        int s;
        if (t < 64) {
            int q0 = __shfl_sync(FULLMASK, i0, t & 31);
            int q1 = __shfl_sync(FULLMASK, i1, t & 31);
            s = (t < 32) ? q0 : q1;
        } else s = valid ? g_srcpad[base + t] : node;
        uint4 v = __ldcg(reinterpret_cast<const uint4*>(&g_h1h[(size_t)s * 32 + f * 8]));
        if (valid) add_row(accB, v);
    }

    __half2 hv[4];
    pack_accs(accA, accB, hv);
    hreduce_level(hv, 4);
    hreduce_level(hv, 8);
    hreduce_level(hv, 16);

    if (e == 0) {
        float acc[8];
        hacc_to_float(hv, acc);
        uint4 sv = *reinterpret_cast<const uint4*>(&g_h1h[(size_t)node * 32 + f * 8]);
        float sf[8];
        unpack_row(sf, sv);
        float z[8];
#pragma unroll
        for (int i = 0; i < 8; i++)
            z[i] = fmaxf(fmaf(di, acc[i] + sf[i], b1s[8 * f + i]), 0.0f);
        *reinterpret_cast<uint4*>(&g_z1[(size_t)node * 32 + f * 8]) = pack_row(z);
    }
}

// ---------------- GEMM2: h2' = (z1 @ W2) * dinv  (8 nodes/warp) ----------------
__global__ void k_gemm2(const float* __restrict__ W2, int n) {
    __shared__ float W2t[64 * W2T_S];       // W2t[o*W2T_S + k] = W2[k][o]
    __shared__ float zs[8][8][32];
    int tid = threadIdx.x;
    for (int idx = tid; idx < 32 * 64; idx += 256) {
        int k = idx >> 6, o = idx & 63;
        W2t[o * W2T_S + k] = W2[idx];
    }
    __syncthreads();

    int lane = tid & 31;
    int w    = tid >> 5;
    int node0 = (blockIdx.x * 8 + w) * 8;

    {
        int t = lane >> 2, i = lane & 3;
        int nd = node0 + t;
        float zf[8] = {0.f, 0.f, 0.f, 0.f, 0.f, 0.f, 0.f, 0.f};
        if (nd < n) {
            uint4 v = *reinterpret_cast<const uint4*>(&g_z1[(size_t)nd * 32 + i * 8]);
            unpack_row(zf, v);
        }
        *reinterpret_cast<float4*>(&zs[w][t][i * 8])     = *reinterpret_cast<float4*>(&zf[0]);
        *reinterpret_cast<float4*>(&zs[w][t][i * 8 + 4]) = *reinterpret_cast<float4*>(&zf[4]);
    }
    __syncwarp();

    float m0[8] = {0.f, 0.f, 0.f, 0.f, 0.f, 0.f, 0.f, 0.f};
    float m1[8] = {0.f, 0.f, 0.f, 0.f, 0.f, 0.f, 0.f, 0.f};
#pragma unroll
    for (int k4 = 0; k4 < 8; k4++) {
        float4 w0 = *reinterpret_cast<float4*>(&W2t[lane * W2T_S + k4 * 4]);
        float4 w1 = *reinterpret_cast<float4*>(&W2t[(lane + 32) * W2T_S + k4 * 4]);
#pragma unroll
        for (int t = 0; t < 8; t++) {
            float4 zv = *reinterpret_cast<float4*>(&zs[w][t][k4 * 4]);
            m0[t] = fmaf(zv.x, w0.x, fmaf(zv.y, w0.y, fmaf(zv.z, w0.z, fmaf(zv.w, w0.w, m0[t]))));
            m1[t] = fmaf(zv.x, w1.x, fmaf(zv.y, w1.y, fmaf(zv.z, w1.z, fmaf(zv.w, w1.w, m1[t]))));
        }
    }
#pragma unroll
    for (int t = 0; t < 8; t++) {
        int nd = node0 + t;
        if (nd < n) {
            float dvt = g_dinv[nd];
            g_h2h[(size_t)nd * 64 + lane]      = __float2half(m0[t] * dvt);
            g_h2h[(size_t)nd * 64 + 32 + lane] = __float2half(m1[t] * dvt);
        }
    }
}

// ---------------- agg2 (pure): z2 = relu(di*(sum + self) + b2) ----------------
// warp per node; e = lane>>3, q = lane&7. 16-edge first pass: 4 LDGs in flight.
__global__ void k_agg2(const float* __restrict__ b2, int n) {
    __shared__ float b2s[64];
    int tid = threadIdx.x;
    if (tid < 64) b2s[tid] = b2[tid];
    __syncthreads();

    int lane = tid & 31;
    int w    = tid >> 5;
    int node = blockIdx.x * 8 + w;
    if (node >= n) return;

    int e = lane >> 3;
    int q = lane & 7;

    float di   = g_dinv[node];
    int   base = node << PADSH;
    int   cnt  = g_cnt[node]; if (cnt > PAD) cnt = PAD;

    int i0 = g_srcpad[base + lane];
    int i1 = (cnt > 32) ? g_srcpad[base + 32 + lane] : 0;
    int cregs = (cnt < 64) ? cnt : 64;

    float accA[8] = {0.f, 0.f, 0.f, 0.f, 0.f, 0.f, 0.f, 0.f};
    float accB[8] = {0.f, 0.f, 0.f, 0.f, 0.f, 0.f, 0.f, 0.f};

    int j = 0;
    // 16 edges / iter: 4 independent LDG.128 in flight
    for (; j + 16 <= cregs; j += 16) {
        int selA = ((j)      < 32) ? i0 : i1;
        int selB = ((j + 4)  < 32) ? i0 : i1;
        int selC = ((j + 8)  < 32) ? i0 : i1;
        int selD = ((j + 12) < 32) ? i0 : i1;
        int sA = __shfl_sync(FULLMASK, selA, (j + e) & 31);
        int sB = __shfl_sync(FULLMASK, selB, (j + 4 + e) & 31);
        int sC = __shfl_sync(FULLMASK, selC, (j + 8 + e) & 31);
        int sD = __shfl_sync(FULLMASK, selD, (j + 12 + e) & 31);
        uint4 vA = __ldcg(reinterpret_cast<const uint4*>(&g_h2h[(size_t)sA * 64 + q * 8]));
        uint4 vB = __ldcg(reinterpret_cast<const uint4*>(&g_h2h[(size_t)sB * 64 + q * 8]));
        uint4 vC = __ldcg(reinterpret_cast<const uint4*>(&g_h2h[(size_t)sC * 64 + q * 8]));
        uint4 vD = __ldcg(reinterpret_cast<const uint4*>(&g_h2h[(size_t)sD * 64 + q * 8]));
        add_row(accA, vA);
        add_row(accB, vB);
        add_row(accA, vC);
        add_row(accB, vD);
    }
    // 8 edges / iter
    for (; j + 8 <= cregs; j += 8) {
        int selA = (j < 32) ? i0 : i1;
        int selB = ((j + 4) < 32) ? i0 : i1;
        int sA = __shfl_sync(FULLMASK, selA, (j + e) & 31);
        int sB = __shfl_sync(FULLMASK, selB, (j + 4 + e) & 31);
        uint4 vA = __ldcg(reinterpret_cast<const uint4*>(&g_h2h[(size_t)sA * 64 + q * 8]));
        uint4 vB = __ldcg(reinterpret_cast<const uint4*>(&g_h2h[(size_t)sB * 64 + q * 8]));
        add_row(accA, vA);
        add_row(accB, vB);
    }
    if (j + 4 <= cregs) {
        int sel = (j < 32) ? i0 : i1;
        int s = __shfl_sync(FULLMASK, sel, (j + e) & 31);
        uint4 v = __ldcg(reinterpret_cast<const uint4*>(&g_h2h[(size_t)s * 64 + q * 8]));
        add_row(accA, v);
        j += 4;
    }
    for (; j + 4 <= cnt; j += 4) {          // degree > 64 (rare)
        int s = g_srcpad[base + j + e];
        uint4 v = __ldcg(reinterpret_cast<const uint4*>(&g_h2h[(size_t)s * 64 + q * 8]));
        add_row(accA, v);
    }
    if (j < cnt) {                          // tail < 4
        int t = j + e;
        bool valid = t < cnt;
        int s;
        if (t < 64) {
            int q0 = __shfl_sync(FULLMASK, i0, t & 31);
            int q1 = __shfl_sync(FULLMASK, i1, t & 31);
            s = (t < 32) ? q0 : q1;
        } else s = valid ? g_srcpad[base + t] : node;
        uint4 v = __ldcg(reinterpret_cast<const uint4*>(&g_h2h[(size_t)s * 64 + q * 8]));
        if (valid) add_row(accB, v);
    }

    __half2 hv[4];
    pack_accs(accA, accB, hv);
    hreduce_level(hv, 8);
    hreduce_level(hv, 16);

    if (e == 0) {
        float acc[8];
        hacc_to_float(hv, acc);
        uint4 sv = *reinterpret_cast<const uint4*>(&g_h2h[(size_t)node * 64 + q * 8]);
        float sf[8];
        unpack_row(sf, sv);
        float z[8];
#pragma unroll
        for (int i = 0; i < 8; i++)
            z[i] = fmaxf(fmaf(di, acc[i] + sf[i], b2s[8 * q + i]), 0.0f);
        *reinterpret_cast<uint4*>(&g_z2[(size_t)node * 64 + q * 8]) = pack_row(z);
    }
}

// ---------------- MLP head + scaled atomic output + g_cnt reset (8 nodes/warp) ----------------
__global__ void k_mlp(const float* __restrict__ Wm1, const float* __restrict__ bm1,
                      const float* __restrict__ Wm2, const float* __restrict__ bm2,
                      float* __restrict__ out,
                      int n, int num_nodes, int nbatch, float inv_num_nodes) {
    __shared__ float Wm1t[64 * WM1T_S];
    __shared__ float zs[8][8][64];
    __shared__ float bm1s[64];
    __shared__ float Wm2s[64];
    __shared__ float pv[64];
    __shared__ int   pb[64];

    int tid = threadIdx.x;
    for (int idx = tid; idx < 64 * 64; idx += 256) {
        int k = idx >> 6, o = idx & 63;
        Wm1t[o * WM1T_S + k] = Wm1[idx];
    }
    if (tid < 64) { bm1s[tid] = bm1[tid]; Wm2s[tid] = Wm2[tid]; }
    __syncthreads();

    int lane = tid & 31;
    int w    = tid >> 5;
    int node0 = (blockIdx.x * 8 + w) * 8;

#pragma unroll
    for (int r = 0; r < 2; r++) {
        int idx = r * 32 + lane;
        int t = idx >> 3, i = idx & 7;
        int nd = node0 + t;
        float zf[8] = {0.f, 0.f, 0.f, 0.f, 0.f, 0.f, 0.f, 0.f};
        if (nd < n) {
            uint4 v = *reinterpret_cast<const uint4*>(&g_z2[(size_t)nd * 64 + i * 8]);
            unpack_row(zf, v);
        }
        *reinterpret_cast<float4*>(&zs[w][t][i * 8])     = *reinterpret_cast<float4*>(&zf[0]);
        *reinterpret_cast<float4*>(&zs[w][t][i * 8 + 4]) = *reinterpret_cast<float4*>(&zf[4]);
    }
    __syncwarp();

    float m0[8], m1[8];
#pragma unroll
    for (int t = 0; t < 8; t++) { m0[t] = bm1s[lane]; m1[t] = bm1s[lane + 32]; }

#pragma unroll
    for (int k4 = 0; k4 < 16; k4++) {
        float4 w0 = *reinterpret_cast<float4*>(&Wm1t[lane * WM1T_S + k4 * 4]);
        float4 w1 = *reinterpret_cast<float4*>(&Wm1t[(lane + 32) * WM1T_S + k4 * 4]);
#pragma unroll
        for (int t = 0; t < 8; t++) {
            float4 zv = *reinterpret_cast<float4*>(&zs[w][t][k4 * 4]);
            m0[t] = fmaf(zv.x, w0.x, fmaf(zv.y, w0.y, fmaf(zv.z, w0.z, fmaf(zv.w, w0.w, m0[t]))));
            m1[t] = fmaf(zv.x, w1.x, fmaf(zv.y, w1.y, fmaf(zv.z, w1.z, fmaf(zv.w, w1.w, m1[t]))));
        }
    }

    float wa = Wm2s[lane], wb = Wm2s[lane + 32];
#pragma unroll
    for (int t = 0; t < 8; t++) {
        float p = fmaxf(m0[t], 0.f) * wa + fmaxf(m1[t], 0.f) * wb;
        p += __shfl_xor_sync(FULLMASK, p, 16);
        p += __shfl_xor_sync(FULLMASK, p, 8);
        p += __shfl_xor_sync(FULLMASK, p, 4);
        p += __shfl_xor_sync(FULLMASK, p, 2);
        p += __shfl_xor_sync(FULLMASK, p, 1);
        if (lane == 0) {
            int nd = node0 + t;
            bool act = nd < n;
            pv[w * 8 + t] = act ? (p + bm2[0]) : 0.0f;
            int b = act ? (nd / num_nodes) : -1;
            if (b >= nbatch) b = -1;
            pb[w * 8 + t] = b;
        }
    }
    __syncthreads();

    if (tid == 0) {
        int bA = -1, bB = -1; float sA = 0.f, sB = 0.f;
        for (int k = 0; k < 64; k++) {
            int b = pb[k];
            if (b < 0) continue;
            if (bA < 0 || b == bA) { bA = b; sA += pv[k]; }
            else                   { bB = b; sB += pv[k]; }
        }
        if (bA >= 0) atomicAdd(&out[bA], sA * inv_num_nodes);
        if (bB >= 0) atomicAdd(&out[bB], sB * inv_num_nodes);
    }

    // reset g_cnt for the next graph replay (k_mlp never reads g_cnt; last kernel)
    int gi = blockIdx.x * blockDim.x + tid;
    if (gi < n) g_cnt[gi] = 0;
}

// ---------------- host launch ----------------
extern "C" void kernel_launch(void* const* d_in, const int* in_sizes, int n_in,
                              void* d_out, int out_size) {
    const float* x   = (const float*)d_in[0];
    const float* W1c = (const float*)d_in[1];
    const float* b1c = (const float*)d_in[2];
    const float* W2c = (const float*)d_in[3];
    const float* b2c = (const float*)d_in[4];
    const float* Wm1 = (const float*)d_in[5];
    const float* bm1 = (const float*)d_in[6];
    const float* Wm2 = (const float*)d_in[7];
    const float* bm2 = (const float*)d_in[8];
    const int*   ei  = (const int*)d_in[9];
    float* out = (float*)d_out;

    int N = in_sizes[0] / 128;
    int E = in_sizes[9] / 2;
    const int* src = ei;
    const int* dst = ei + E;

    int nbatch = out_size;
    int num_nodes = N / (nbatch > 0 ? nbatch : 1);
    float inv_num_nodes = 1.0f / (float)num_nodes;

    k_fill<<<(E + 255) / 256, 256>>>(src, dst, E, out, nbatch);
    k_gemm1<<<(N + 31) / 32, 256>>>(x, W1c, N);
    k_agg1<<<(N + 7) / 8, 256>>>(b1c, N);
    k_gemm2<<<(N + 63) / 64, 256>>>(W2c, N);
    k_agg2<<<(N + 7) / 8, 256>>>(b2c, N);
    k_mlp<<<(N + 63) / 64, 256>>>(Wm1, bm1, Wm2, bm2, out, N, num_nodes, nbatch, inv_num_nodes);
}